// round 15
// baseline (speedup 1.0000x reference)
#include <cuda_runtime.h>
#include <cstdint>

// ---------------------------------------------------------------------------
// MatrixRouting (EM routing): b=8, Bkk=288, Cww=1152, hh=17, C=32, w=6, 3 iters
// d_out = [ mu_a (8,32,6,6,17) | R (8,288,32,6,6) | votes passthrough ]
// Each CTA: NPAIR=8 consecutive j-pairs for one b, double-buffered cp.async.
// The two j-columns of a pair run on decoupled 256-thread halves with named
// barriers; moments pass uses a Dg=8 half-warp remap (conflict-free LDS).
// Scratch ap/S layout (b, j, i) coalesced; final R via tiled transpose.
// ---------------------------------------------------------------------------

#define EPSV        1e-10f
#define LAMBDA_C    1e-4f
#define HALF_LN_2PI 0.918938533204672741780329736406f
#define LOG2E       1.44269504088896340736f

constexpr int B     = 8;
constexpr int BKK   = 288;
constexpr int CWW   = 1152;
constexpr int HH    = 17;
constexpr int NV    = 16;
constexpr int NCAP  = 32;
constexpr int PP    = 36;
constexpr int SROW  = 34;                       // even: 8B-aligned smem rows
constexpr int NPAIR = 8;                        // j-pairs per CTA

constexpr int MU_A_SIZE = B * NCAP * PP * HH;   // 156672
constexpr int R_SIZE    = B * BKK * CWW;        // 2654208
constexpr int MU_A_OFF  = 0;
constexpr int R_OFF     = MU_A_SIZE;
constexpr int VOTES_OFF = MU_A_SIZE + R_SIZE;

constexpr int VROW   = CWW * HH;                // votes row stride (floats)
constexpr int NCHUNK = BKK * 17;                // 8B chunks per pair = 4896

// scratch (no cudaMalloc allowed)
__device__ float g_ap[B * CWW * BKK];           // layout (b, j, i)
__device__ float g_S[2][B * BKK];               // ping-pong sum_j ap

__global__ void init_S()
{
    int t = blockIdx.x * 256 + threadIdx.x;
    if (t < 2 * B * BKK) ((float*)g_S)[t] = 0.f;
}

__device__ __forceinline__ void cp_async8(float* smem_dst, const float* gmem_src)
{
    uint32_t s = (uint32_t)__cvta_generic_to_shared(smem_dst);
    asm volatile("cp.async.ca.shared.global [%0], [%1], 8;"
                 :: "r"(s), "l"(gmem_src));
}
__device__ __forceinline__ void cp_async16(float* smem_dst, const float* gmem_src)
{
    uint32_t s = (uint32_t)__cvta_generic_to_shared(smem_dst);
    asm volatile("cp.async.cg.shared.global [%0], [%1], 16;"
                 :: "r"(s), "l"(gmem_src));
}
#define CP_COMMIT() asm volatile("cp.async.commit_group;" ::: "memory")
#define CP_WAIT1()  asm volatile("cp.async.wait_group 1;" ::: "memory")
#define CP_WAIT0()  asm volatile("cp.async.wait_group 0;" ::: "memory")
// per-half barrier: id 1+jj, 256 threads
#define BARH(jjv) asm volatile("bar.sync %0, 256;" :: "r"(1 + (jjv)) : "memory")

// ---------------------------------------------------------------------------
// MODE 0: R = 1/32; smem-sourced votes passthrough; writes ap + atomics S[0]
// MODE 1: R from ap/S[0]; writes ap + atomics S[1]
// MODE 2: R from ap/S[1]; writes mu_a; stashes Rw into g_ap (for transpose)
// 512 threads = 2 x 256 (one decoupled half per j column of the pair).
// ---------------------------------------------------------------------------
template <int MODE>
__global__ __launch_bounds__(512, 2)
void mstep(const float* __restrict__ votes,
           const float* __restrict__ beta_v,
           const float* __restrict__ beta_a,
           float* __restrict__ out)
{
    __shared__ __align__(16) float sv[2][BKK * SROW];  // double-buffered tiles
    __shared__ __align__(16) float sap[2][2 * BKK];    // prefetched g_ap slice
    __shared__ float sS[BKK];           // g_S prev for this b (MODE>=1)
    __shared__ float sRw[2 * BKK];      // [jj][i] = R * a_
    __shared__ float sp1[512];          // partials: sum Rw*V   [jj][g][h]
    __shared__ float sp2[512];          // partials: sum Rw*V^2 [jj][g][h]
    __shared__ float smun[2][16];
    __shared__ float ssq[2][16];
    __shared__ float smu[2][16];
    __shared__ float sn2s[2][16];       // (-1/(2 sigma^2)) * log2e
    __shared__ float slnc[2][16];       // (-log_sigma - 0.5 ln2pi) * log2e
    __shared__ float sls[2][16];        // log_sigma
    __shared__ float ssumR[2];
    __shared__ float sa[2];

    const int b     = blockIdx.y;
    const int jbase = blockIdx.x * (2 * NPAIR);
    const int t     = threadIdx.x;
    const int jj    = t >> 8;
    const int tt    = t & 255;

    // ---- one-time: g_S (prev iteration) for this b ----
    if (MODE != 0) {
        const float* Sp = g_S[MODE == 2 ? 1 : 0] + b * BKK;
        for (int i = t; i < BKK; i += 512) sS[i] = Sp[i];
    }

    const float* vbase = votes + (size_t)b * BKK * VROW;

    // ---- async issue of one pair's data: 8B chunks, c = row*17 + sub ----
    auto issue_pair = [&](int p, int st) {
        const int j0 = jbase + 2 * p;
        const float* src0 = vbase + j0 * HH;
        float* dst0 = sv[st];
        for (int c = t; c < NCHUNK; c += 512) {
            int row = c / 17;
            int sub = c - 17 * row;
            cp_async8(dst0 + row * SROW + 2 * sub,
                      src0 + row * VROW + 2 * sub);
        }
        if (MODE != 0) {
            // 576 contiguous floats = 144 float4s (16B-aligned both sides)
            const float* apc = g_ap + ((size_t)b * CWW + j0) * BKK;
            if (t < 144)
                cp_async16(sap[st] + 4 * t, apc + 4 * t);
        }
    };

    issue_pair(0, 0);
    CP_COMMIT();

    for (int p = 0; p < NPAIR; p++) {
        const int st = p & 1;
        const int j0 = jbase + 2 * p;

        if (p + 1 < NPAIR) { issue_pair(p + 1, st ^ 1); CP_COMMIT(); CP_WAIT1(); }
        else               { CP_WAIT0(); }
        __syncthreads();                 // pair p data visible to all threads

        const float* svb = sv[st];

        // ---- MODE 0: votes passthrough (each half copies its row range) ----
        if (MODE == 0) {
            float* dst0 = out + VOTES_OFF + (size_t)b * BKK * VROW + j0 * HH;
            for (int cc = tt; cc < NCHUNK / 2; cc += 256) {
                int c   = jj * (NCHUNK / 2) + cc;
                int row = c / 17;
                int sub = c - 17 * row;
                *(float2*)(dst0 + row * VROW + 2 * sub) =
                    *(const float2*)(svb + row * SROW + 2 * sub);
            }
        }

        // ---- Rw = R * a_  (own half; all operands in smem) ----
        for (int i = tt; i < BKK; i += 256) {
            float av = svb[i * SROW + jj * 17 + 16];
            float r;
            if (MODE == 0) {
                r = av * (1.0f / 32.0f);
            } else {
                r = (sap[st][jj * BKK + i] / (sS[i] + EPSV) + EPSV) * av;
            }
            sRw[jj * BKK + i] = r;
        }
        BARH(jj);

        // ---- moments (own half): Dg=8 half-warp remap -> conflict-free ----
        {
            int h  = tt & 15;
            int g  = (tt >> 5) + 8 * ((tt >> 4) & 1);   // 0..15
            const float* col = svb + jj * 17 + h;
            const float* rw  = sRw + jj * BKK;
            float a1 = 0.f, a2 = 0.f;
            #pragma unroll 6
            for (int i = g; i < BKK; i += 16) {
                float r  = rw[i];
                float v  = col[i * SROW];
                float rv = r * v;
                a1 += rv;
                a2 = fmaf(rv, v, a2);
            }
            sp1[jj * 256 + g * 16 + h] = a1;
            sp2[jj * 256 + g * 16 + h] = a2;
        }
        BARH(jj);

        // ---- fold partials (half's warp 0) + raw sumR (half's warp 1) ----
        if (tt < 32) {
            int h = tt & 15;
            float s = 0.f;
            if (tt < 16) {
                #pragma unroll
                for (int g = 0; g < 16; g++) s += sp1[jj * 256 + g * 16 + h];
                smun[jj][h] = s;
            } else {
                #pragma unroll
                for (int g = 0; g < 16; g++) s += sp2[jj * 256 + g * 16 + h];
                ssq[jj][h] = s;
            }
        } else if (tt < 64) {
            int l = tt - 32;
            const float* rw = sRw + jj * BKK;
            float s = 0.f;
            #pragma unroll
            for (int k = 0; k < 9; k++) s += rw[l + 32 * k];
            #pragma unroll
            for (int o = 16; o; o >>= 1) s += __shfl_down_sync(0xffffffffu, s, o);
            if (l == 0) ssumR[jj] = s;
        }
        BARH(jj);

        // ---- stats (half's warp 0, lanes 0-15) + activation (lane 0) ----
        if (tt < 32) {
            if (tt < 16) {
                int h = tt;
                float Sr = ssumR[jj];
                float Sp = Sr + 1e-4f;
                float n1 = smun[jj][h];
                float mu = n1 / Sp;
                float sig = (ssq[jj][h] - 2.f * mu * n1 + (mu * mu + EPSV) * Sr)
                            / Sp + EPSV;
                float ls = __logf(sqrtf(sig) + EPSV);
                smu[jj][h]  = mu;
                sn2s[jj][h] = (-0.5f / sig) * LOG2E;
                slnc[jj][h] = (-ls - HALF_LN_2PI) * LOG2E;
                sls[jj][h]  = ls;
            }
            __syncwarp();
            if (tt == 0) {
                float lsum = 0.f;
                #pragma unroll
                for (int h = 0; h < 16; h++) lsum += sls[jj][h];
                int c = (j0 + jj) / PP;
                float cost = (16.0f * beta_v[c] + lsum) * (ssumR[jj] + 1e-4f);
                float x = LAMBDA_C * (beta_a[c] - cost);
                sa[jj] = 1.0f / (1.0f + __expf(-x));
            }
        }
        BARH(jj);

        if (MODE < 2) {
            // ---- E-step (own half): ap = a * sum_h exp(ln_p); fused S ----
            float a = sa[jj];
            float* apw   = g_ap + ((size_t)b * CWW + j0 + jj) * BKK;
            float* Snext = g_S[MODE == 0 ? 0 : 1] + b * BKK;
            for (int i = tt; i < BKK; i += 256) {
                const float* row = svb + i * SROW + jj * 17;
                float p_ = 0.f;
                #pragma unroll 8
                for (int h = 0; h < NV; h++) {
                    float d = row[h] - smu[jj][h];
                    float e = fmaf(fmaf(d, d, EPSV), sn2s[jj][h], slnc[jj][h]);
                    float r;
                    asm("ex2.approx.ftz.f32 %0, %1;" : "=f"(r) : "f"(e));
                    p_ += r;
                }
                float ap = a * p_;
                apw[i] = ap;                    // coalesced
                atomicAdd(&Snext[i], ap);       // coalesced REDG
            }
        } else {
            // ---- final: stash Rw into g_ap (own half); write mu_a ----
            float* apw = g_ap + ((size_t)b * CWW + j0 + jj) * BKK;
            for (int i = tt; i < BKK; i += 256)
                apw[i] = sRw[jj * BKK + i];
            if (tt < HH) {
                int j = j0 + jj;
                int c = j / PP, ppos = j - c * PP;
                float v = (tt < NV) ? smu[jj][tt] : sa[jj];
                out[MU_A_OFF + ((b * NCAP + c) * PP + ppos) * HH + tt] = v;
            }
        }
        __syncthreads();    // protect buffer st before next-next issue
    }
}

// ---------------------------------------------------------------------------
// R output: transpose g_ap (b, j, i) -> out (b, i, j), 32x32 smem tiles.
// ---------------------------------------------------------------------------
__global__ __launch_bounds__(256)
void transposeR(float* __restrict__ out)
{
    __shared__ float tile[32][33];
    const int bb = blockIdx.z;
    const int j0 = blockIdx.x * 32;
    const int i0 = blockIdx.y * 32;
    const int tx = threadIdx.x, ty = threadIdx.y;   // 32 x 8

    const float* src = g_ap + ((size_t)bb * CWW + j0) * BKK + i0;
    #pragma unroll
    for (int k = 0; k < 32; k += 8)
        tile[ty + k][tx] = src[(ty + k) * BKK + tx];
    __syncthreads();

    float* dst = out + R_OFF + ((size_t)bb * BKK + i0) * CWW + j0;
    #pragma unroll
    for (int k = 0; k < 32; k += 8)
        dst[(ty + k) * CWW + tx] = tile[tx][ty + k];
}

// ---------------------------------------------------------------------------
extern "C" void kernel_launch(void* const* d_in, const int* in_sizes, int n_in,
                              void* d_out, int out_size)
{
    const float* votes  = (const float*)d_in[0];
    const float* beta_v = (const float*)d_in[1];
    const float* beta_a = (const float*)d_in[2];
    float* out = (float*)d_out;

    dim3 grid(CWW / (2 * NPAIR), B);   // (72, 8)

    init_S<<<(2 * B * BKK + 255) / 256, 256>>>();
    mstep<0><<<grid, 512>>>(votes, beta_v, beta_a, out);  // iter0 + votes copy
    mstep<1><<<grid, 512>>>(votes, beta_v, beta_a, out);  // iter1
    mstep<2><<<grid, 512>>>(votes, beta_v, beta_a, out);  // iter2 + mu_a
    transposeR<<<dim3(CWW / 32, BKK / 32, B), dim3(32, 8)>>>(out);
}

// round 17
// speedup vs baseline: 1.3630x; 1.3630x over previous
#include <cuda_runtime.h>
#include <cstdint>

// ---------------------------------------------------------------------------
// MatrixRouting (EM routing): b=8, Bkk=288, Cww=1152, hh=17, C=32, w=6, 3 iters
// d_out = [ mu_a (8,32,6,6,17) | R (8,288,32,6,6) | votes passthrough ]
// Each CTA processes NPAIR=16 consecutive j-pairs for one b (288 CTAs = one
// wave at 2 CTAs/SM), double-buffered: cp.async 8B chunks (flat c/17 indexing)
// prefetch pair p+1 while pair p computes. Scratch ap/S layout (b, j, i)
// coalesced; final R via tiled transpose.
// ---------------------------------------------------------------------------

#define EPSV        1e-10f
#define LAMBDA_C    1e-4f
#define HALF_LN_2PI 0.918938533204672741780329736406f
#define LOG2E       1.44269504088896340736f

constexpr int B     = 8;
constexpr int BKK   = 288;
constexpr int CWW   = 1152;
constexpr int HH    = 17;
constexpr int NV    = 16;
constexpr int NCAP  = 32;
constexpr int PP    = 36;
constexpr int SROW  = 34;                       // even: 8B-aligned smem rows
constexpr int NPAIR = 16;                       // j-pairs per CTA (one wave)

constexpr int MU_A_SIZE = B * NCAP * PP * HH;   // 156672
constexpr int R_SIZE    = B * BKK * CWW;        // 2654208
constexpr int MU_A_OFF  = 0;
constexpr int R_OFF     = MU_A_SIZE;
constexpr int VOTES_OFF = MU_A_SIZE + R_SIZE;

constexpr int VROW   = CWW * HH;                // votes row stride (floats)
constexpr int NCHUNK = BKK * 17;                // 8B chunks per pair = 4896

// scratch (no cudaMalloc allowed)
__device__ float g_ap[B * CWW * BKK];           // layout (b, j, i)
__device__ float g_S[2][B * BKK];               // ping-pong sum_j ap

__global__ void init_S()
{
    int t = blockIdx.x * 256 + threadIdx.x;
    if (t < 2 * B * BKK) ((float*)g_S)[t] = 0.f;
}

__device__ __forceinline__ void cp_async8(float* smem_dst, const float* gmem_src)
{
    uint32_t s = (uint32_t)__cvta_generic_to_shared(smem_dst);
    asm volatile("cp.async.ca.shared.global [%0], [%1], 8;"
                 :: "r"(s), "l"(gmem_src));
}
__device__ __forceinline__ void cp_async16(float* smem_dst, const float* gmem_src)
{
    uint32_t s = (uint32_t)__cvta_generic_to_shared(smem_dst);
    asm volatile("cp.async.cg.shared.global [%0], [%1], 16;"
                 :: "r"(s), "l"(gmem_src));
}
#define CP_COMMIT() asm volatile("cp.async.commit_group;" ::: "memory")
#define CP_WAIT1()  asm volatile("cp.async.wait_group 1;" ::: "memory")
#define CP_WAIT0()  asm volatile("cp.async.wait_group 0;" ::: "memory")

// ---------------------------------------------------------------------------
// MODE 0: R = 1/32; smem-sourced votes passthrough; writes ap + atomics S[0]
// MODE 1: R from ap/S[0]; writes ap + atomics S[1]
// MODE 2: R from ap/S[1]; writes mu_a; stashes Rw into g_ap (for transpose)
// 512 threads = 2 x 256 (one half per j column of the pair).
// ---------------------------------------------------------------------------
template <int MODE>
__global__ __launch_bounds__(512, 2)
void mstep(const float* __restrict__ votes,
           const float* __restrict__ beta_v,
           const float* __restrict__ beta_a,
           float* __restrict__ out)
{
    __shared__ __align__(16) float sv[2][BKK * SROW];  // double-buffered tiles
    __shared__ __align__(16) float sap[2][2 * BKK];    // prefetched g_ap slice
    __shared__ float sS[BKK];           // g_S prev for this b (MODE>=1)
    __shared__ float sRw[2 * BKK];      // [jj][i] = R * a_
    __shared__ float sp1[512];          // partial sum Rw*V
    __shared__ float sp2[512];          // partial sum Rw*V^2
    __shared__ float smun[2][16];
    __shared__ float ssq[2][16];
    __shared__ float smu[2][16];
    __shared__ float sn2s[2][16];       // (-1/(2 sigma^2)) * log2e
    __shared__ float slnc[2][16];       // (-log_sigma - 0.5 ln2pi) * log2e
    __shared__ float ssumR[2];
    __shared__ float sa[2];

    const int b     = blockIdx.y;
    const int jbase = blockIdx.x * (2 * NPAIR);
    const int t     = threadIdx.x;
    const int jj    = t >> 8;
    const int tt    = t & 255;

    // ---- one-time: g_S (prev iteration) for this b ----
    if (MODE != 0) {
        const float* Sp = g_S[MODE == 2 ? 1 : 0] + b * BKK;
        for (int i = t; i < BKK; i += 512) sS[i] = Sp[i];
    }

    const float* vbase = votes + (size_t)b * BKK * VROW;

    // ---- async issue of one pair's data: 8B chunks, c = row*17 + sub ----
    auto issue_pair = [&](int p, int st) {
        const int j0 = jbase + 2 * p;
        const float* src0 = vbase + j0 * HH;
        float* dst0 = sv[st];
        for (int c = t; c < NCHUNK; c += 512) {
            int row = c / 17;
            int sub = c - 17 * row;
            cp_async8(dst0 + row * SROW + 2 * sub,
                      src0 + row * VROW + 2 * sub);
        }
        if (MODE != 0) {
            // 576 contiguous floats = 144 float4s (16B-aligned both sides)
            const float* apc = g_ap + ((size_t)b * CWW + j0) * BKK;
            if (t < 144)
                cp_async16(sap[st] + 4 * t, apc + 4 * t);
        }
    };

    issue_pair(0, 0);
    CP_COMMIT();

    for (int p = 0; p < NPAIR; p++) {
        const int st = p & 1;
        const int j0 = jbase + 2 * p;

        if (p + 1 < NPAIR) { issue_pair(p + 1, st ^ 1); CP_COMMIT(); CP_WAIT1(); }
        else               { CP_WAIT0(); }
        __syncthreads();                 // pair p data visible to all threads

        const float* svb = sv[st];

        // ---- MODE 0: votes passthrough from smem (8B, same decomposition) --
        if (MODE == 0) {
            float* dst0 = out + VOTES_OFF + (size_t)b * BKK * VROW + j0 * HH;
            for (int c = t; c < NCHUNK; c += 512) {
                int row = c / 17;
                int sub = c - 17 * row;
                *(float2*)(dst0 + row * VROW + 2 * sub) =
                    *(const float2*)(svb + row * SROW + 2 * sub);
            }
        }

        // ---- Rw = R * a_  (all operands in smem) ----
        for (int i = tt; i < BKK; i += 256) {
            float av = svb[i * SROW + jj * 17 + 16];
            float r;
            if (MODE == 0) {
                r = av * (1.0f / 32.0f);
            } else {
                r = (sap[st][jj * BKK + i] / (sS[i] + EPSV) + EPSV) * av;
            }
            sRw[jj * BKK + i] = r;
        }
        __syncthreads();

        // ---- single moments pass: sum Rw*V, sum Rw*V^2 per (jj,h) ----
        {
            int h = tt & 15, g = tt >> 4;
            const float* col = svb + jj * 17 + h;
            const float* rw  = sRw + jj * BKK;
            float a1 = 0.f, a2 = 0.f;
            #pragma unroll 6
            for (int i = g; i < BKK; i += 16) {
                float r  = rw[i];
                float v  = col[i * SROW];
                float rv = r * v;
                a1 += rv;
                a2 = fmaf(rv, v, a2);
            }
            sp1[t] = a1;
            sp2[t] = a2;
        }
        __syncthreads();

        // ---- fold partials; raw sum Rw in warps 2,3 ----
        if (t < 32) {
            int jp = t >> 4, h = t & 15;
            float s = 0.f;
            #pragma unroll
            for (int g = 0; g < 16; g++) s += sp1[jp * 256 + g * 16 + h];
            smun[jp][h] = s;
        } else if (t < 64) {
            int u = t - 32, jp = u >> 4, h = u & 15;
            float s = 0.f;
            #pragma unroll
            for (int g = 0; g < 16; g++) s += sp2[jp * 256 + g * 16 + h];
            ssq[jp][h] = s;
        } else if (t < 128) {
            int jp = (t >> 5) - 2, l = t & 31;
            const float* rw = sRw + jp * BKK;
            float s = 0.f;
            #pragma unroll 3
            for (int i = l; i < BKK; i += 32) s += rw[i];
            #pragma unroll
            for (int o = 16; o; o >>= 1) s += __shfl_down_sync(0xffffffffu, s, o);
            if (l == 0) ssumR[jp] = s;
        }
        __syncthreads();

        // ---- mu, sigma, consts, activation (warp 0 only) ----
        if (t < 32) {
            int jp = t >> 4, h = t & 15;
            float Sr = ssumR[jp];
            float Sp = Sr + 1e-4f;
            float n1 = smun[jp][h];
            float mu = n1 / Sp;
            float sig = (ssq[jp][h] - 2.f * mu * n1 + (mu * mu + EPSV) * Sr) / Sp
                        + EPSV;
            float ls = __logf(sqrtf(sig) + EPSV);
            smu[jp][h]  = mu;
            sn2s[jp][h] = (-0.5f / sig) * LOG2E;
            slnc[jp][h] = (-ls - HALF_LN_2PI) * LOG2E;
            float lsum = ls;
            #pragma unroll
            for (int k = 1; k < 16; k <<= 1)
                lsum += __shfl_xor_sync(0xffffffffu, lsum, k);
            if (h == 0) {
                int c = (j0 + jp) / PP;
                float cost = (16.0f * beta_v[c] + lsum) * Sp;
                float x = LAMBDA_C * (beta_a[c] - cost);
                sa[jp] = 1.0f / (1.0f + __expf(-x));
            }
        }
        __syncthreads();

        if (MODE < 2) {
            // ---- E-step: ap = a * sum_h exp(ln_p); fused S accumulation ----
            float a = sa[jj];
            float* apw   = g_ap + ((size_t)b * CWW + j0 + jj) * BKK;
            float* Snext = g_S[MODE == 0 ? 0 : 1] + b * BKK;
            for (int i = tt; i < BKK; i += 256) {
                const float* row = svb + i * SROW + jj * 17;
                float p_ = 0.f;
                #pragma unroll 8
                for (int h = 0; h < NV; h++) {
                    float d = row[h] - smu[jj][h];
                    float e = fmaf(fmaf(d, d, EPSV), sn2s[jj][h], slnc[jj][h]);
                    float r;
                    asm("ex2.approx.ftz.f32 %0, %1;" : "=f"(r) : "f"(e));
                    p_ += r;
                }
                float ap = a * p_;
                apw[i] = ap;                    // coalesced
                atomicAdd(&Snext[i], ap);       // coalesced REDG
            }
        } else {
            // ---- final: stash Rw into g_ap (coalesced); write mu_a ----
            float* apw = g_ap + ((size_t)b * CWW + j0 + jj) * BKK;
            for (int i = tt; i < BKK; i += 256)
                apw[i] = sRw[jj * BKK + i];
            if (t < 2 * HH) {
                int jp = t / HH, h = t - jp * HH;
                int j = j0 + jp;
                int c = j / PP, ppos = j - c * PP;
                float v = (h < NV) ? smu[jp][h] : sa[jp];
                out[MU_A_OFF + ((b * NCAP + c) * PP + ppos) * HH + h] = v;
            }
        }
        __syncthreads();    // protect buffer st before next-next issue
    }
}

// ---------------------------------------------------------------------------
// R output: transpose g_ap (b, j, i) -> out (b, i, j), 32x32 smem tiles.
// ---------------------------------------------------------------------------
__global__ __launch_bounds__(256)
void transposeR(float* __restrict__ out)
{
    __shared__ float tile[32][33];
    const int bb = blockIdx.z;
    const int j0 = blockIdx.x * 32;
    const int i0 = blockIdx.y * 32;
    const int tx = threadIdx.x, ty = threadIdx.y;   // 32 x 8

    const float* src = g_ap + ((size_t)bb * CWW + j0) * BKK + i0;
    #pragma unroll
    for (int k = 0; k < 32; k += 8)
        tile[ty + k][tx] = src[(ty + k) * BKK + tx];
    __syncthreads();

    float* dst = out + R_OFF + ((size_t)bb * BKK + i0) * CWW + j0;
    #pragma unroll
    for (int k = 0; k < 32; k += 8)
        dst[(ty + k) * CWW + tx] = tile[tx][ty + k];
}

// ---------------------------------------------------------------------------
extern "C" void kernel_launch(void* const* d_in, const int* in_sizes, int n_in,
                              void* d_out, int out_size)
{
    const float* votes  = (const float*)d_in[0];
    const float* beta_v = (const float*)d_in[1];
    const float* beta_a = (const float*)d_in[2];
    float* out = (float*)d_out;

    dim3 grid(CWW / (2 * NPAIR), B);   // (36, 8) = 288 CTAs: one wave

    init_S<<<(2 * B * BKK + 255) / 256, 256>>>();
    mstep<0><<<grid, 512>>>(votes, beta_v, beta_a, out);  // iter0 + votes copy
    mstep<1><<<grid, 512>>>(votes, beta_v, beta_a, out);  // iter1
    mstep<2><<<grid, 512>>>(votes, beta_v, beta_a, out);  // iter2 + mu_a
    transposeR<<<dim3(CWW / 32, BKK / 32, B), dim3(32, 8)>>>(out);
}